// round 6
// baseline (speedup 1.0000x reference)
#include <cuda_runtime.h>

#define A_N 500000
#define G_N 64
#define K1_TPB 256
#define K1_IPA 2                              /* anchors per thread      */
#define K1_TILE (K1_TPB * K1_IPA)             /* 512                     */
#define NB1 ((A_N + K1_TILE - 1) / K1_TILE)   /* 977                     */
#define R_FLOOR 0.02f

// ---------------- scratch (device globals; no allocations allowed) ----------
__device__ unsigned long long g_blk_best[G_N * NB1]; // per-(gt,block) approx best
__device__ int g_flags[A_N];                         // 0 none, 1 pos, 2 neg
__device__ int g_cnt_pos[NB1], g_cnt_neg[NB1];
__device__ int g_pos_sel[128], g_neg_sel[128];

// NOTE: named u64max to avoid collision with sbsa math_functions.hpp::ullmax
static __device__ __forceinline__ unsigned long long u64max(unsigned long long a,
                                                            unsigned long long b) {
    return a > b ? a : b;
}

// ---------------- K1: IoU sweep -> flags + counts + per-(gt,block) best -----
// Branch-free mainloop (outer x4, inner x16 full-unroll => ~10KB body, fits
// I$). Candidate bits (iou > R_FLOOR, one sign-exact FMA) go into a u64 mask;
// candidates resolved in a short ffs walk after the loop (approx MUFU division
// for ranking key + shadow-guarded shared atomics). Exactness restored in K2.
// Per-block pos/neg counts are reduced here (K2 patches them for forced pos).
__global__ void __launch_bounds__(K1_TPB) k1_iou(const float4* __restrict__ anchors,
                                                 const float4* __restrict__ gts) {
    __shared__ float4 s_g[G_N];
    __shared__ float s_area[G_N];
    __shared__ int s_r[G_N];                       // float bits, monotone >= 0
    __shared__ unsigned long long s_key[G_N];      // (approx_iou_bits<<32)|rev
    __shared__ int s_cnt[8];

    int t = threadIdx.x;
    if (t < G_N) {
        float4 g = gts[t];
        s_g[t] = g;
        s_area[t] = __fmul_rn(__fsub_rn(g.z, g.x), __fsub_rn(g.w, g.y));
        s_r[t] = __float_as_int(R_FLOOR);
        s_key[t] = 0ull;
    }
    __syncthreads();

    int i0 = blockIdx.x * K1_TILE + t;
    int i1 = i0 + K1_TPB;
    bool v0 = (i0 < A_N), v1 = (i1 < A_N);
    float4 a0 = v0 ? anchors[i0] : make_float4(0.f, 0.f, 0.f, 0.f);
    float4 a1 = v1 ? anchors[i1] : make_float4(0.f, 0.f, 0.f, 0.f);
    float ar0 = __fmul_rn(__fsub_rn(a0.z, a0.x), __fsub_rn(a0.w, a0.y));
    float ar1 = __fmul_rn(__fsub_rn(a1.z, a1.x), __fsub_rn(a1.w, a1.y));
    unsigned rev0 = 0xFFFFFFFFu - (unsigned)i0;
    unsigned rev1 = 0xFFFFFFFFu - (unsigned)i1;

    float posm0 = -1.f, negm0 = -1.f, posm1 = -1.f, negm1 = -1.f;
    unsigned long long m0 = 0ull, m1 = 0ull;

#pragma unroll 1
    for (int go = 0; go < G_N; go += 16) {
        unsigned mm0 = 0u, mm1 = 0u;
#pragma unroll
        for (int k = 0; k < 16; ++k) {
            int g = go + k;
            float4 gb = s_g[g];
            float ag = s_area[g];
            // pair 0
            float wx0 = fmaxf(__fsub_rn(fminf(a0.z, gb.z), fmaxf(a0.x, gb.x)), 0.f);
            float wy0 = fmaxf(__fsub_rn(fminf(a0.w, gb.w), fmaxf(a0.y, gb.y)), 0.f);
            float in0 = __fmul_rn(wx0, wy0);
            float un0 = __fsub_rn(__fadd_rn(ar0, ag), in0);
            posm0 = fmaxf(posm0, __fmaf_rn(2.0f, in0, -un0));   // sign <=> iou>0.5
            negm0 = fmaxf(negm0, __fmaf_rn(-0.3f, un0, in0));   // sign <=> iou>=0.3
            mm0 |= (__fmaf_rn(R_FLOOR, un0, -in0) < 0.0f) ? (1u << k) : 0u;
            // pair 1
            float wx1 = fmaxf(__fsub_rn(fminf(a1.z, gb.z), fmaxf(a1.x, gb.x)), 0.f);
            float wy1 = fmaxf(__fsub_rn(fminf(a1.w, gb.w), fmaxf(a1.y, gb.y)), 0.f);
            float in1 = __fmul_rn(wx1, wy1);
            float un1 = __fsub_rn(__fadd_rn(ar1, ag), in1);
            posm1 = fmaxf(posm1, __fmaf_rn(2.0f, in1, -un1));
            negm1 = fmaxf(negm1, __fmaf_rn(-0.3f, un1, in1));
            mm1 |= (__fmaf_rn(R_FLOOR, un1, -in1) < 0.0f) ? (1u << k) : 0u;
        }
        m0 |= (unsigned long long)mm0 << go;
        m1 |= (unsigned long long)mm1 << go;
    }

    int f0 = (posm0 > 0.0f) ? 1 : ((negm0 < 0.0f) ? 2 : 0);
    int f1 = (posm1 > 0.0f) ? 1 : ((negm1 < 0.0f) ? 2 : 0);
    if (v0) g_flags[i0] = f0;
    if (v1) g_flags[i1] = f1;
    if (!v0) { m0 = 0ull; f0 = 0; }
    if (!v1) { m1 = 0ull; f1 = 0; }

    // deferred candidate resolution (rare: E[popc] ~ 1-2 per pair)
    while (m0) {
        int g = __ffsll((long long)m0) - 1;
        m0 &= m0 - 1ull;
        float4 gb = s_g[g];
        float wx = fmaxf(__fsub_rn(fminf(a0.z, gb.z), fmaxf(a0.x, gb.x)), 0.f);
        float wy = fmaxf(__fsub_rn(fminf(a0.w, gb.w), fmaxf(a0.y, gb.y)), 0.f);
        float inter = __fmul_rn(wx, wy);
        float uni = __fsub_rn(__fadd_rn(ar0, s_area[g]), inter);
        int ival = __float_as_int(__fdividef(inter, uni));
        if (ival >= s_r[g]) {     // >= keeps equal-iou lower-index candidates
            atomicMax(&s_r[g], ival);
            atomicMax(&s_key[g], ((unsigned long long)(unsigned)ival << 32) |
                                 (unsigned long long)rev0);
        }
    }
    while (m1) {
        int g = __ffsll((long long)m1) - 1;
        m1 &= m1 - 1ull;
        float4 gb = s_g[g];
        float wx = fmaxf(__fsub_rn(fminf(a1.z, gb.z), fmaxf(a1.x, gb.x)), 0.f);
        float wy = fmaxf(__fsub_rn(fminf(a1.w, gb.w), fmaxf(a1.y, gb.y)), 0.f);
        float inter = __fmul_rn(wx, wy);
        float uni = __fsub_rn(__fadd_rn(ar1, s_area[g]), inter);
        int ival = __float_as_int(__fdividef(inter, uni));
        if (ival >= s_r[g]) {
            atomicMax(&s_r[g], ival);
            atomicMax(&s_key[g], ((unsigned long long)(unsigned)ival << 32) |
                                 (unsigned long long)rev1);
        }
    }

    // per-block pos/neg counts (register flags; K2 patches forced positives)
    int packed = ((f0 == 1) + (f1 == 1)) | ((((f0 == 2) + (f1 == 2))) << 16);
    for (int o = 16; o > 0; o >>= 1) packed += __shfl_down_sync(0xFFFFFFFFu, packed, o);
    if ((t & 31) == 0) s_cnt[t >> 5] = packed;
    __syncthreads();   // also orders s_key/s_r atomics before the export below
    if (t < G_N) g_blk_best[t * NB1 + blockIdx.x] = s_key[t];
    if (t == 0) {
        int tot = 0;
#pragma unroll
        for (int k = 0; k < 8; ++k) tot += s_cnt[k];
        g_cnt_pos[blockIdx.x] = tot & 0xFFFF;
        g_cnt_neg[blockIdx.x] = tot >> 16;
    }
}

// ---------------- K2: per-GT exact argmax -> force positive + patch counts --
__global__ void __launch_bounds__(256) k2_gtbest(const float4* __restrict__ anchors,
                                                 const float4* __restrict__ gts) {
    __shared__ unsigned long long s[256];
    int g = blockIdx.x, t = threadIdx.x;
    float4 gb = gts[g];
    float ag = __fmul_rn(__fsub_rn(gb.z, gb.x), __fsub_rn(gb.w, gb.y));

    unsigned long long best = 0ull;
    const unsigned long long* row = g_blk_best + (size_t)g * NB1;
    for (int b = t; b < NB1; b += 256) {
        unsigned long long k = row[b];
        if (k == 0ull) continue;
        unsigned idx = 0xFFFFFFFFu - (unsigned)(k & 0xFFFFFFFFull);
        if (idx >= A_N) continue;
        float4 a = anchors[idx];
        float area_a = __fmul_rn(__fsub_rn(a.z, a.x), __fsub_rn(a.w, a.y));
        float wx = fmaxf(__fsub_rn(fminf(a.z, gb.z), fmaxf(a.x, gb.x)), 0.f);
        float wy = fmaxf(__fsub_rn(fminf(a.w, gb.w), fmaxf(a.y, gb.y)), 0.f);
        float inter = __fmul_rn(wx, wy);
        float uni = __fsub_rn(__fadd_rn(area_a, ag), inter);
        float iou = __fdiv_rn(inter, uni);   // exact (matches reference bits)
        unsigned long long key =
            ((unsigned long long)(unsigned)__float_as_int(iou) << 32) |
            (unsigned long long)(0xFFFFFFFFu - idx);
        best = u64max(best, key);
    }
    s[t] = best;
    __syncthreads();
    for (int o = 128; o > 0; o >>= 1) {
        if (t < o) s[t] = u64max(s[t], s[t + o]);
        __syncthreads();
    }
    if (t == 0 && s[0] != 0ull) {
        unsigned idx = 0xFFFFFFFFu - (unsigned)(s[0] & 0xFFFFFFFFull);
        if (idx < A_N) {
            int old = atomicExch(&g_flags[idx], 1);  // exactly-once vs dup gts
            if (old != 1) {
                int b = (int)(idx / K1_TILE);
                atomicAdd(&g_cnt_pos[b], 1);
                if (old == 2) atomicSub(&g_cnt_neg[b], 1);
            }
        }
    }
}

// ---------------- K5: ordered first-128 compaction w/ inline prefix ---------
// Each block computes its own exclusive prefix over the (patched) per-block
// counts -- kills the separate scan kernel. Counts packed pos|neg<<32 in u64
// (neg prefix can reach ~490K; 16 bits is per-block-only).
__global__ void __launch_bounds__(128) k5_select() {
    __shared__ unsigned long long s_pref[4];
    __shared__ int ws[4];
    int b = blockIdx.x, t = threadIdx.x;
    int lane = t & 31, warp = t >> 5;

    // exclusive prefix of counts [0, b)
    unsigned long long pref = 0ull;
    for (int i = t; i < b; i += 128)
        pref += (unsigned long long)(unsigned)g_cnt_pos[i] |
                ((unsigned long long)(unsigned)g_cnt_neg[i] << 32);
    for (int o = 16; o > 0; o >>= 1)
        pref += __shfl_down_sync(0xFFFFFFFFu, pref, o);
    if (lane == 0) s_pref[warp] = pref;
    __syncthreads();
    unsigned long long tot = s_pref[0] + s_pref[1] + s_pref[2] + s_pref[3];
    int pos_base = (int)(tot & 0xFFFFFFFFull);
    int neg_base = (int)(tot >> 32);
    if (pos_base >= 128 && neg_base >= 128) return;  // uniform per-block exit

    int base = b * K1_TILE + t * 4;
    int f[4];
    if (base + 3 < A_N) {
        int4 w = *(const int4*)(g_flags + base);
        f[0] = w.x; f[1] = w.y; f[2] = w.z; f[3] = w.w;
    } else {
#pragma unroll
        for (int k = 0; k < 4; ++k)
            f[k] = (base + k < A_N) ? g_flags[base + k] : 0;
    }
    int p = 0, n = 0;
#pragma unroll
    for (int k = 0; k < 4; ++k) {
        p += (f[k] == 1);
        n += (f[k] == 2);
    }
    int packed = p | (n << 16);
    int x = packed;
    for (int o = 1; o < 32; o <<= 1) {
        int y = __shfl_up_sync(0xFFFFFFFFu, x, o);
        if (lane >= o) x += y;
    }
    if (lane == 31) ws[warp] = x;
    __syncthreads();
    int wof = 0;
    for (int k = 0; k < warp; ++k) wof += ws[k];
    int excl = x - packed + wof;
    int pr = pos_base + (excl & 0xFFFF);
    int nr = neg_base + (excl >> 16);
#pragma unroll
    for (int k = 0; k < 4; ++k) {
        if (f[k] == 1) {
            if (pr < 128) g_pos_sel[pr] = base + k;
            pr++;
        } else if (f[k] == 2) {
            if (nr < 128) g_neg_sel[nr] = base + k;
            nr++;
        }
    }
}

static __device__ __forceinline__ float sl1(float x) {
    float ax = fabsf(x);
    return ax < 1.0f ? 0.5f * x * x : ax - 0.5f;
}

// ---------------- K6: losses over <=128 pos + <=128 neg ---------------------
__global__ void __launch_bounds__(128) k6_loss(const float* __restrict__ score,
                                               const float* __restrict__ reg,
                                               const float4* __restrict__ anchors,
                                               const float4* __restrict__ gts,
                                               float* __restrict__ out) {
    __shared__ float4 s_g[G_N];
    __shared__ float sA[128], sB[128];
    __shared__ unsigned long long s_tot[4];
    int t = threadIdx.x;
    int lane = t & 31, warp = t >> 5;
    if (t < G_N) s_g[t] = gts[t];

    // totals (replaces scan kernel's g_total_*)
    unsigned long long tot = 0ull;
    for (int i = t; i < NB1; i += 128)
        tot += (unsigned long long)(unsigned)g_cnt_pos[i] |
               ((unsigned long long)(unsigned)g_cnt_neg[i] << 32);
    for (int o = 16; o > 0; o >>= 1)
        tot += __shfl_down_sync(0xFFFFFFFFu, tot, o);
    if (lane == 0) s_tot[warp] = tot;
    __syncthreads();
    tot = s_tot[0] + s_tot[1] + s_tot[2] + s_tot[3];
    int tp = (int)(tot & 0xFFFFFFFFull);
    int tn = (int)(tot >> 32);

    int npos = tp < 128 ? tp : 128;
    bool bug = (tp >= 128);
    int nbound = bug ? 128 : tp;
    int nneg = nbound < tn ? nbound : tn;

    float a_sum = 0.f, b_sum = 0.f;
    if (t < npos) {
        int ai = g_pos_sel[t];
        float4 a = anchors[ai];
        float area_a = __fmul_rn(__fsub_rn(a.z, a.x), __fsub_rn(a.w, a.y));
        // recompute anchor_argmax exactly (div.rn, strict >, first occurrence)
        float best = -1.0f;
        int bg = 0;
        for (int g = 0; g < G_N; ++g) {
            float4 gb = s_g[g];
            float wx = fmaxf(__fsub_rn(fminf(a.z, gb.z), fmaxf(a.x, gb.x)), 0.f);
            float wy = fmaxf(__fsub_rn(fminf(a.w, gb.w), fmaxf(a.y, gb.y)), 0.f);
            float inter = __fmul_rn(wx, wy);
            float agv = __fmul_rn(__fsub_rn(gb.z, gb.x), __fsub_rn(gb.w, gb.y));
            float uni = __fsub_rn(__fadd_rn(area_a, agv), inter);
            float iou = __fdiv_rn(inter, uni);
            if (iou > best) { best = iou; bg = g; }
        }
        // positive classification loss (target = 0)
        float cls;
        if (bug) {  // reference "bug": anchor coords used as 4-way logits
            float v0 = a.x, v1 = a.y, v2 = a.z, v3 = a.w;
            float m = fmaxf(fmaxf(v0, v1), fmaxf(v2, v3));
            float s = expf(v0 - m) + expf(v1 - m) + expf(v2 - m) + expf(v3 - m);
            cls = logf(s) - (v0 - m);
        } else {
            float v0 = score[2 * ai], v1 = score[2 * ai + 1];
            float m = fmaxf(v0, v1);
            float s = expf(v0 - m) + expf(v1 - m);
            cls = logf(s) - (v0 - m);
        }
        // regression loss
        float4 gb = s_g[bg];
        float aw = a.z - a.x, ah = a.w - a.y;
        float acx = a.x + aw * 0.5f, acy = a.y + ah * 0.5f;
        float gw = gb.z - gb.x, gh = gb.w - gb.y;
        float gcx = gb.x + gw * 0.5f, gcy = gb.y + gh * 0.5f;
        float tx = (gcx - acx) / aw, ty = (gcy - acy) / ah;
        float tw = logf(gw / aw), th = logf(gh / ah);
        const float* r = reg + 4 * ai;
        float rs = sl1(r[0] - tx) + sl1(r[1] - ty) + sl1(r[2] - tw) + sl1(r[3] - th);
        a_sum = cls + rs;
    }
    if (t < nneg) {
        int ni = g_neg_sel[t];
        float v0 = score[2 * ni], v1 = score[2 * ni + 1];
        float m = fmaxf(v0, v1);
        float s = expf(v0 - m) + expf(v1 - m);
        b_sum = logf(s) - (v1 - m);   // target = 1
    }
    sA[t] = a_sum;
    sB[t] = b_sum;
    __syncthreads();
    for (int o = 64; o > 0; o >>= 1) {
        if (t < o) { sA[t] += sA[t + o]; sB[t] += sB[t + o]; }
        __syncthreads();
    }
    if (t == 0)
        out[0] = sA[0] / (float)npos + sB[0] / (float)nneg;
}

// ---------------- launch ----------------------------------------------------
extern "C" void kernel_launch(void* const* d_in, const int* in_sizes, int n_in,
                              void* d_out, int out_size) {
    const float* score = (const float*)d_in[0];     // [A,2]
    const float* reg = (const float*)d_in[1];       // [A,4]
    const float4* anchors = (const float4*)d_in[2]; // [A,4]
    const float4* gts = (const float4*)d_in[3];     // [G,4]
    (void)in_sizes; (void)n_in; (void)out_size;

    k1_iou<<<NB1, K1_TPB>>>(anchors, gts);
    k2_gtbest<<<G_N, 256>>>(anchors, gts);
    k5_select<<<NB1, 128>>>();
    k6_loss<<<1, 128>>>(score, reg, anchors, gts, (float*)d_out);
}

// round 9
// speedup vs baseline: 1.3495x; 1.3495x over previous
#include <cuda_runtime.h>

#define A_N 500000
#define G_N 64
#define K1_TPB 256
#define NB1 ((A_N + K1_TPB - 1) / K1_TPB)   /* 1954 */
#define R_FLOOR 0.02f
#define BIN_W 32.0f
#define BIN_INV 0.03125f                    /* 1/32: power of two => exact */

// ---------------- scratch (device globals; no allocations allowed) ----------
__device__ unsigned long long g_blk_best[G_N * NB1]; // per-(gt,block) approx best
__device__ int g_flags[A_N];                         // 0 none, 1 pos, 2 neg
__device__ int g_cnt_pos[NB1], g_cnt_neg[NB1];
__device__ int g_pos_sel[128], g_neg_sel[128];

// named u64max to avoid collision with sbsa math_functions.hpp::ullmax
static __device__ __forceinline__ unsigned long long u64max(unsigned long long a,
                                                            unsigned long long b) {
    return a > b ? a : b;
}

static __device__ __forceinline__ int bin_of(float v) {
    int b = (int)(v * BIN_INV);         // exact scale (power-of-two)
    return b < 0 ? 0 : (b > 31 ? 31 : b);
}

// ---------------- K1: binned IoU sweep -> flags + counts + (gt,block) best --
// Phase A: candidate mask = ~(gts entirely left|right|below|above) via 4
// bin-table LDS -- superset of overlapping gts. Phase B: sparse ffs walk with
// exact threshold FMAs; approx MUFU division feeds the shadow-guarded
// per-(block,gt) best key (exactness restored in K2).
__global__ void __launch_bounds__(K1_TPB) k1_iou(const float4* __restrict__ anchors,
                                                 const float4* __restrict__ gts) {
    __shared__ float4 s_g[G_N];
    __shared__ float s_area[G_N];
    __shared__ int s_r[G_N];                       // float bits, monotone
    __shared__ unsigned long long s_key[G_N];      // (approx_iou_bits<<32)|rev
    __shared__ unsigned long long s_tbl[4][32];    // Lx, Rx, Ly, Ry
    __shared__ int s_cw[8];

    int t = threadIdx.x;
    if (t < G_N) {
        float4 g = gts[t];
        s_g[t] = g;
        s_area[t] = __fmul_rn(__fsub_rn(g.z, g.x), __fsub_rn(g.w, g.y));
        s_r[t] = __float_as_int(R_FLOOR);
        s_key[t] = 0ull;
    }
    __syncthreads();

    if (t < 128) {                 // build disjointness tables (4 tables x 32)
        int tbl = t >> 5, b = t & 31;
        float eL = (float)b * BIN_W;
        float eR = eL + BIN_W;
        unsigned long long mask = 0ull;
        for (int g = 0; g < G_N; ++g) {
            float4 gb = s_g[g];
            bool out;
            if (tbl == 0)      out = gb.z < eL;   // entirely left  of bin start
            else if (tbl == 1) out = gb.x > eR;   // entirely right of bin end
            else if (tbl == 2) out = gb.w < eL;   // entirely below
            else               out = gb.y > eR;   // entirely above
            mask |= out ? (1ull << g) : 0ull;
        }
        s_tbl[tbl][b] = mask;
    }
    __syncthreads();

    int i = blockIdx.x * K1_TPB + t;
    bool valid = (i < A_N);
    float4 a = valid ? anchors[i] : make_float4(0.f, 0.f, 0.f, 0.f);
    float ar = __fmul_rn(__fsub_rn(a.z, a.x), __fsub_rn(a.w, a.y));
    unsigned rev = 0xFFFFFFFFu - (unsigned)i;

    unsigned long long m =
        ~(s_tbl[0][bin_of(a.x)] | s_tbl[1][bin_of(a.z)] |
          s_tbl[2][bin_of(a.y)] | s_tbl[3][bin_of(a.w)]);
    if (!valid) m = 0ull;

    float posm = -1.f, negm = -1.f;
    while (m) {
        int g = __ffsll((long long)m) - 1;
        m &= m - 1ull;
        float4 gb = s_g[g];
        float wx = fmaxf(__fsub_rn(fminf(a.z, gb.z), fmaxf(a.x, gb.x)), 0.f);
        float wy = fmaxf(__fsub_rn(fminf(a.w, gb.w), fmaxf(a.y, gb.y)), 0.f);
        float inter = __fmul_rn(wx, wy);
        float uni = __fsub_rn(__fadd_rn(ar, s_area[g]), inter);
        posm = fmaxf(posm, __fmaf_rn(2.0f, inter, -uni));   // sign <=> iou>0.5
        negm = fmaxf(negm, __fmaf_rn(-0.3f, uni, inter));   // sign <=> iou>=0.3
        int ival = __float_as_int(__fdividef(inter, uni));  // ranking key only
        if (ival >= s_r[g]) {   // iou<R_FLOOR auto-fails; >= keeps tie lower idx
            atomicMax(&s_r[g], ival);
            atomicMax(&s_key[g], ((unsigned long long)(unsigned)ival << 32) |
                                 (unsigned long long)rev);
        }
    }

    int f = (posm > 0.0f) ? 1 : ((negm < 0.0f) ? 2 : 0);
    if (valid) g_flags[i] = f;
    if (!valid) f = 0;

    // per-block pos/neg counts via ballots (K2 patches forced positives)
    unsigned bp = __ballot_sync(0xFFFFFFFFu, f == 1);
    unsigned bn = __ballot_sync(0xFFFFFFFFu, f == 2);
    if ((t & 31) == 0) s_cw[t >> 5] = __popc(bp) | (__popc(bn) << 16);
    __syncthreads();   // also orders s_key/s_r atomics before the export below
    if (t < G_N) g_blk_best[t * NB1 + blockIdx.x] = s_key[t];
    if (t == 0) {
        int tot = 0;
#pragma unroll
        for (int k = 0; k < 8; ++k) tot += s_cw[k];
        g_cnt_pos[blockIdx.x] = tot & 0xFFFF;
        g_cnt_neg[blockIdx.x] = tot >> 16;
    }
}

// ---------------- K2: per-GT exact argmax -> force positive + patch counts --
__global__ void __launch_bounds__(256) k2_gtbest(const float4* __restrict__ anchors,
                                                 const float4* __restrict__ gts) {
    __shared__ unsigned long long s[256];
    int g = blockIdx.x, t = threadIdx.x;
    float4 gb = gts[g];
    float ag = __fmul_rn(__fsub_rn(gb.z, gb.x), __fsub_rn(gb.w, gb.y));

    unsigned long long best = 0ull;
    const unsigned long long* row = g_blk_best + (size_t)g * NB1;
    for (int b = t; b < NB1; b += 256) {
        unsigned long long k = row[b];
        if (k == 0ull) continue;
        unsigned idx = 0xFFFFFFFFu - (unsigned)(k & 0xFFFFFFFFull);
        if (idx >= A_N) continue;
        float4 a = anchors[idx];
        float area_a = __fmul_rn(__fsub_rn(a.z, a.x), __fsub_rn(a.w, a.y));
        float wx = fmaxf(__fsub_rn(fminf(a.z, gb.z), fmaxf(a.x, gb.x)), 0.f);
        float wy = fmaxf(__fsub_rn(fminf(a.w, gb.w), fmaxf(a.y, gb.y)), 0.f);
        float inter = __fmul_rn(wx, wy);
        float uni = __fsub_rn(__fadd_rn(area_a, ag), inter);
        float iou = __fdiv_rn(inter, uni);   // exact (matches reference bits)
        unsigned long long key =
            ((unsigned long long)(unsigned)__float_as_int(iou) << 32) |
            (unsigned long long)(0xFFFFFFFFu - idx);
        best = u64max(best, key);
    }
    s[t] = best;
    __syncthreads();
    for (int o = 128; o > 0; o >>= 1) {
        if (t < o) s[t] = u64max(s[t], s[t + o]);
        __syncthreads();
    }
    if (t == 0 && s[0] != 0ull) {
        unsigned idx = 0xFFFFFFFFu - (unsigned)(s[0] & 0xFFFFFFFFull);
        if (idx < A_N) {
            int old = atomicExch(&g_flags[idx], 1);  // exactly-once vs dup gts
            if (old != 1) {
                int b = (int)(idx / K1_TPB);
                atomicAdd(&g_cnt_pos[b], 1);
                if (old == 2) atomicSub(&g_cnt_neg[b], 1);
            }
        }
    }
}

// ---------------- K5: ordered first-128 compaction w/ inline prefix ---------
__global__ void __launch_bounds__(256) k5_select() {
    __shared__ unsigned long long s_pref[8];
    __shared__ int s_wp[8], s_wn[8];
    int b = blockIdx.x, t = threadIdx.x;
    int lane = t & 31, warp = t >> 5;

    // exclusive prefix of counts [0, b), packed pos|neg<<32
    unsigned long long pref = 0ull;
    for (int i = t; i < b; i += 256)
        pref += (unsigned long long)(unsigned)g_cnt_pos[i] |
                ((unsigned long long)(unsigned)g_cnt_neg[i] << 32);
    for (int o = 16; o > 0; o >>= 1)
        pref += __shfl_down_sync(0xFFFFFFFFu, pref, o);
    if (lane == 0) s_pref[warp] = pref;
    __syncthreads();
    unsigned long long tot = 0ull;
#pragma unroll
    for (int k = 0; k < 8; ++k) tot += s_pref[k];
    int pos_base = (int)(tot & 0xFFFFFFFFull);
    int neg_base = (int)(tot >> 32);
    if (pos_base >= 128 && neg_base >= 128) return;  // uniform per-block exit

    int i = b * K1_TPB + t;
    int f = (i < A_N) ? g_flags[i] : 0;
    unsigned bp = __ballot_sync(0xFFFFFFFFu, f == 1);
    unsigned bn = __ballot_sync(0xFFFFFFFFu, f == 2);
    if (lane == 0) { s_wp[warp] = __popc(bp); s_wn[warp] = __popc(bn); }
    __syncthreads();
    int wop = 0, won = 0;
    for (int k = 0; k < warp; ++k) { wop += s_wp[k]; won += s_wn[k]; }
    unsigned lt = (1u << lane) - 1u;
    int pr = pos_base + wop + __popc(bp & lt);
    int nr = neg_base + won + __popc(bn & lt);
    if (f == 1) { if (pr < 128) g_pos_sel[pr] = i; }
    else if (f == 2) { if (nr < 128) g_neg_sel[nr] = i; }
}

static __device__ __forceinline__ float sl1(float x) {
    float ax = fabsf(x);
    return ax < 1.0f ? 0.5f * x * x : ax - 0.5f;
}

// ---------------- K6: losses, 1024 threads, 8 threads per positive ----------
__global__ void __launch_bounds__(1024) k6_loss(const float* __restrict__ score,
                                                const float* __restrict__ reg,
                                                const float4* __restrict__ anchors,
                                                const float4* __restrict__ gts,
                                                float* __restrict__ out) {
    __shared__ float4 s_g[G_N];
    __shared__ unsigned long long s_tot[32];
    __shared__ float sA[32], sB[32];
    int t = threadIdx.x;
    int lane = t & 31, warp = t >> 5;
    if (t < G_N) s_g[t] = gts[t];

    // totals over per-block counts
    unsigned long long tot = 0ull;
    for (int i = t; i < NB1; i += 1024)
        tot += (unsigned long long)(unsigned)g_cnt_pos[i] |
               ((unsigned long long)(unsigned)g_cnt_neg[i] << 32);
    for (int o = 16; o > 0; o >>= 1)
        tot += __shfl_down_sync(0xFFFFFFFFu, tot, o);
    if (lane == 0) s_tot[warp] = tot;
    __syncthreads();
    if (warp == 0) {
        unsigned long long v = s_tot[lane];
        for (int o = 16; o > 0; o >>= 1)
            v += __shfl_down_sync(0xFFFFFFFFu, v, o);
        if (lane == 0) s_tot[0] = v;
    }
    __syncthreads();
    tot = s_tot[0];
    int tp = (int)(tot & 0xFFFFFFFFull);
    int tn = (int)(tot >> 32);

    int npos = tp < 128 ? tp : 128;
    bool bug = (tp >= 128);
    int nneg = npos < tn ? npos : tn;      // nbound == npos in both branches

    // positives: 8 threads each; per-thread 8 gts (exact div.rn, ILP-friendly)
    int pid = t >> 3, sub = t & 7;
    bool pvalid = (pid < npos);
    int ai = pvalid ? g_pos_sel[pid] : 0;
    float4 a = anchors[ai];
    float area_a = __fmul_rn(__fsub_rn(a.z, a.x), __fsub_rn(a.w, a.y));
    unsigned long long bk = 0ull;
#pragma unroll
    for (int j = 0; j < 8; ++j) {
        int g = sub * 8 + j;
        float4 gb = s_g[g];
        float wx = fmaxf(__fsub_rn(fminf(a.z, gb.z), fmaxf(a.x, gb.x)), 0.f);
        float wy = fmaxf(__fsub_rn(fminf(a.w, gb.w), fmaxf(a.y, gb.y)), 0.f);
        float inter = __fmul_rn(wx, wy);
        float agv = __fmul_rn(__fsub_rn(gb.z, gb.x), __fsub_rn(gb.w, gb.y));
        float uni = __fsub_rn(__fadd_rn(area_a, agv), inter);
        float iou = __fdiv_rn(inter, uni);       // exact, matches reference
        // key: max iou wins; ties -> largest (63-g) = smallest g (first occur)
        unsigned long long key =
            ((unsigned long long)(unsigned)__float_as_int(iou) << 6) |
            (unsigned long long)(unsigned)(63 - g);
        bk = u64max(bk, key);
    }
    bk = u64max(bk, __shfl_xor_sync(0xFFFFFFFFu, bk, 1));
    bk = u64max(bk, __shfl_xor_sync(0xFFFFFFFFu, bk, 2));
    bk = u64max(bk, __shfl_xor_sync(0xFFFFFFFFu, bk, 4));

    float a_val = 0.f;
    if (pvalid && sub == 0) {
        int bg = 63 - (int)(bk & 63ull);
        float cls;
        if (bug) {  // reference "bug": anchor coords used as 4-way logits
            float v0 = a.x, v1 = a.y, v2 = a.z, v3 = a.w;
            float mx = fmaxf(fmaxf(v0, v1), fmaxf(v2, v3));
            float s = expf(v0 - mx) + expf(v1 - mx) + expf(v2 - mx) + expf(v3 - mx);
            cls = logf(s) - (v0 - mx);
        } else {
            float v0 = score[2 * ai], v1 = score[2 * ai + 1];
            float mx = fmaxf(v0, v1);
            float s = expf(v0 - mx) + expf(v1 - mx);
            cls = logf(s) - (v0 - mx);
        }
        float4 gb = s_g[bg];
        float aw = a.z - a.x, ah = a.w - a.y;
        float acx = a.x + aw * 0.5f, acy = a.y + ah * 0.5f;
        float gw = gb.z - gb.x, gh = gb.w - gb.y;
        float gcx = gb.x + gw * 0.5f, gcy = gb.y + gh * 0.5f;
        float tx = (gcx - acx) / aw, ty = (gcy - acy) / ah;
        float tw = logf(gw / aw), th = logf(gh / ah);
        const float* r = reg + 4 * ai;
        float rs = sl1(r[0] - tx) + sl1(r[1] - ty) + sl1(r[2] - tw) + sl1(r[3] - th);
        a_val = cls + rs;
    }

    float b_val = 0.f;
    if (t < nneg) {
        int ni = g_neg_sel[t];
        float v0 = score[2 * ni], v1 = score[2 * ni + 1];
        float mx = fmaxf(v0, v1);
        float s = expf(v0 - mx) + expf(v1 - mx);
        b_val = logf(s) - (v1 - mx);   // target = 1
    }

    // block reduce both sums
    for (int o = 16; o > 0; o >>= 1) {
        a_val += __shfl_down_sync(0xFFFFFFFFu, a_val, o);
        b_val += __shfl_down_sync(0xFFFFFFFFu, b_val, o);
    }
    if (lane == 0) { sA[warp] = a_val; sB[warp] = b_val; }
    __syncthreads();
    if (warp == 0) {
        float av = sA[lane], bv = sB[lane];
        for (int o = 16; o > 0; o >>= 1) {
            av += __shfl_down_sync(0xFFFFFFFFu, av, o);
            bv += __shfl_down_sync(0xFFFFFFFFu, bv, o);
        }
        if (lane == 0)
            out[0] = av / (float)npos + bv / (float)nneg;
    }
}

// ---------------- launch ----------------------------------------------------
extern "C" void kernel_launch(void* const* d_in, const int* in_sizes, int n_in,
                              void* d_out, int out_size) {
    const float* score = (const float*)d_in[0];     // [A,2]
    const float* reg = (const float*)d_in[1];       // [A,4]
    const float4* anchors = (const float4*)d_in[2]; // [A,4]
    const float4* gts = (const float4*)d_in[3];     // [G,4]
    (void)in_sizes; (void)n_in; (void)out_size;

    k1_iou<<<NB1, K1_TPB>>>(anchors, gts);
    k2_gtbest<<<G_N, 256>>>(anchors, gts);
    k5_select<<<NB1, 256>>>();
    k6_loss<<<1, 1024>>>(score, reg, anchors, gts, (float*)d_out);
}

// round 10
// speedup vs baseline: 1.4111x; 1.0457x over previous
#include <cuda_runtime.h>

#define A_N 500000
#define G_N 64
#define K1_TPB 256
#define NB1 ((A_N + K1_TPB - 1) / K1_TPB)   /* 1954 */
#define R_FLOOR 0.02f
#define BIN_W 32.0f
#define BIN_INV 0.03125f                    /* 1/32: power of two => exact */

// ---------------- scratch (device globals; no allocations allowed) ----------
__device__ unsigned long long g_blk_best[G_N * NB1]; // per-(gt,block) approx best
__device__ int g_flags[A_N];                         // 0 none, 1 pos, 2 neg
__device__ int g_cnt_pos[NB1], g_cnt_neg[NB1];
__device__ int g_pos_sel[128], g_neg_sel[128];
__device__ float g_pos_loss[128];

// named u64max to avoid collision with sbsa math_functions.hpp::ullmax
static __device__ __forceinline__ unsigned long long u64max(unsigned long long a,
                                                            unsigned long long b) {
    return a > b ? a : b;
}

static __device__ __forceinline__ int bin_of(float v) {
    int b = (int)(v * BIN_INV);         // exact scale (power-of-two)
    return b < 0 ? 0 : (b > 31 ? 31 : b);
}

// ---------------- K1: binned IoU sweep -> flags + counts + (gt,block) best --
__global__ void __launch_bounds__(K1_TPB) k1_iou(const float4* __restrict__ anchors,
                                                 const float4* __restrict__ gts) {
    __shared__ float4 s_g[G_N];
    __shared__ float s_area[G_N];
    __shared__ int s_r[G_N];                       // float bits, monotone
    __shared__ unsigned long long s_key[G_N];      // (approx_iou_bits<<32)|rev
    __shared__ unsigned long long s_tbl[4][32];    // Lx, Rx, Ly, Ry
    __shared__ int s_cw[8];

    int t = threadIdx.x;
    if (t < G_N) {
        float4 g = gts[t];
        s_g[t] = g;
        s_area[t] = __fmul_rn(__fsub_rn(g.z, g.x), __fsub_rn(g.w, g.y));
        s_r[t] = __float_as_int(R_FLOOR);
        s_key[t] = 0ull;
    }
    __syncthreads();

    if (t < 128) {                 // build disjointness tables (4 tables x 32)
        int tbl = t >> 5, b = t & 31;
        float eL = (float)b * BIN_W;
        float eR = eL + BIN_W;
        unsigned long long mask = 0ull;
        for (int g = 0; g < G_N; ++g) {
            float4 gb = s_g[g];
            bool out;
            if (tbl == 0)      out = gb.z < eL;   // entirely left  of bin start
            else if (tbl == 1) out = gb.x > eR;   // entirely right of bin end
            else if (tbl == 2) out = gb.w < eL;   // entirely below
            else               out = gb.y > eR;   // entirely above
            mask |= out ? (1ull << g) : 0ull;
        }
        s_tbl[tbl][b] = mask;
    }
    __syncthreads();

    int i = blockIdx.x * K1_TPB + t;
    bool valid = (i < A_N);
    float4 a = valid ? anchors[i] : make_float4(0.f, 0.f, 0.f, 0.f);
    float ar = __fmul_rn(__fsub_rn(a.z, a.x), __fsub_rn(a.w, a.y));
    unsigned rev = 0xFFFFFFFFu - (unsigned)i;

    unsigned long long m =
        ~(s_tbl[0][bin_of(a.x)] | s_tbl[1][bin_of(a.z)] |
          s_tbl[2][bin_of(a.y)] | s_tbl[3][bin_of(a.w)]);
    if (!valid) m = 0ull;

    float posm = -1.f, negm = -1.f;
    while (m) {
        int g = __ffsll((long long)m) - 1;
        m &= m - 1ull;
        float4 gb = s_g[g];
        float wx = fmaxf(__fsub_rn(fminf(a.z, gb.z), fmaxf(a.x, gb.x)), 0.f);
        float wy = fmaxf(__fsub_rn(fminf(a.w, gb.w), fmaxf(a.y, gb.y)), 0.f);
        float inter = __fmul_rn(wx, wy);
        float uni = __fsub_rn(__fadd_rn(ar, s_area[g]), inter);
        posm = fmaxf(posm, __fmaf_rn(2.0f, inter, -uni));   // sign <=> iou>0.5
        negm = fmaxf(negm, __fmaf_rn(-0.3f, uni, inter));   // sign <=> iou>=0.3
        int ival = __float_as_int(__fdividef(inter, uni));  // ranking key only
        if (ival >= s_r[g]) {   // iou<R_FLOOR auto-fails; >= keeps tie lower idx
            atomicMax(&s_r[g], ival);
            atomicMax(&s_key[g], ((unsigned long long)(unsigned)ival << 32) |
                                 (unsigned long long)rev);
        }
    }

    int f = (posm > 0.0f) ? 1 : ((negm < 0.0f) ? 2 : 0);
    if (valid) g_flags[i] = f;
    if (!valid) f = 0;

    // per-block pos/neg counts via ballots (K2 patches forced positives)
    unsigned bp = __ballot_sync(0xFFFFFFFFu, f == 1);
    unsigned bn = __ballot_sync(0xFFFFFFFFu, f == 2);
    if ((t & 31) == 0) s_cw[t >> 5] = __popc(bp) | (__popc(bn) << 16);
    __syncthreads();   // also orders s_key/s_r atomics before the export below
    if (t < G_N) g_blk_best[t * NB1 + blockIdx.x] = s_key[t];
    if (t == 0) {
        int tot = 0;
#pragma unroll
        for (int k = 0; k < 8; ++k) tot += s_cw[k];
        g_cnt_pos[blockIdx.x] = tot & 0xFFFF;
        g_cnt_neg[blockIdx.x] = tot >> 16;
    }
}

// ---------------- K2: per-GT exact argmax -> force positive + patch counts --
__global__ void __launch_bounds__(256) k2_gtbest(const float4* __restrict__ anchors,
                                                 const float4* __restrict__ gts) {
    __shared__ unsigned long long s[256];
    int g = blockIdx.x, t = threadIdx.x;
    float4 gb = gts[g];
    float ag = __fmul_rn(__fsub_rn(gb.z, gb.x), __fsub_rn(gb.w, gb.y));

    unsigned long long best = 0ull;
    const unsigned long long* row = g_blk_best + (size_t)g * NB1;
    for (int b = t; b < NB1; b += 256) {
        unsigned long long k = row[b];
        if (k == 0ull) continue;
        unsigned idx = 0xFFFFFFFFu - (unsigned)(k & 0xFFFFFFFFull);
        if (idx >= A_N) continue;
        float4 a = anchors[idx];
        float area_a = __fmul_rn(__fsub_rn(a.z, a.x), __fsub_rn(a.w, a.y));
        float wx = fmaxf(__fsub_rn(fminf(a.z, gb.z), fmaxf(a.x, gb.x)), 0.f);
        float wy = fmaxf(__fsub_rn(fminf(a.w, gb.w), fmaxf(a.y, gb.y)), 0.f);
        float inter = __fmul_rn(wx, wy);
        float uni = __fsub_rn(__fadd_rn(area_a, ag), inter);
        float iou = __fdiv_rn(inter, uni);   // exact (matches reference bits)
        unsigned long long key =
            ((unsigned long long)(unsigned)__float_as_int(iou) << 32) |
            (unsigned long long)(0xFFFFFFFFu - idx);
        best = u64max(best, key);
    }
    s[t] = best;
    __syncthreads();
    for (int o = 128; o > 0; o >>= 1) {
        if (t < o) s[t] = u64max(s[t], s[t + o]);
        __syncthreads();
    }
    if (t == 0 && s[0] != 0ull) {
        unsigned idx = 0xFFFFFFFFu - (unsigned)(s[0] & 0xFFFFFFFFull);
        if (idx < A_N) {
            int old = atomicExch(&g_flags[idx], 1);  // exactly-once vs dup gts
            if (old != 1) {
                int b = (int)(idx / K1_TPB);
                atomicAdd(&g_cnt_pos[b], 1);
                if (old == 2) atomicSub(&g_cnt_neg[b], 1);
            }
        }
    }
}

// ---------------- K5: ordered first-128 compaction w/ inline prefix ---------
__global__ void __launch_bounds__(256) k5_select() {
    __shared__ unsigned long long s_pref[8];
    __shared__ int s_wp[8], s_wn[8];
    int b = blockIdx.x, t = threadIdx.x;
    int lane = t & 31, warp = t >> 5;

    // exclusive prefix of counts [0, b), packed pos|neg<<32
    unsigned long long pref = 0ull;
    for (int i = t; i < b; i += 256)
        pref += (unsigned long long)(unsigned)g_cnt_pos[i] |
                ((unsigned long long)(unsigned)g_cnt_neg[i] << 32);
    for (int o = 16; o > 0; o >>= 1)
        pref += __shfl_down_sync(0xFFFFFFFFu, pref, o);
    if (lane == 0) s_pref[warp] = pref;
    __syncthreads();
    unsigned long long tot = 0ull;
#pragma unroll
    for (int k = 0; k < 8; ++k) tot += s_pref[k];
    int pos_base = (int)(tot & 0xFFFFFFFFull);
    int neg_base = (int)(tot >> 32);
    if (pos_base >= 128 && neg_base >= 128) return;  // uniform per-block exit

    int i = b * K1_TPB + t;
    int f = (i < A_N) ? g_flags[i] : 0;
    unsigned bp = __ballot_sync(0xFFFFFFFFu, f == 1);
    unsigned bn = __ballot_sync(0xFFFFFFFFu, f == 2);
    if (lane == 0) { s_wp[warp] = __popc(bp); s_wn[warp] = __popc(bn); }
    __syncthreads();
    int wop = 0, won = 0;
    for (int k = 0; k < warp; ++k) { wop += s_wp[k]; won += s_wn[k]; }
    unsigned lt = (1u << lane) - 1u;
    int pr = pos_base + wop + __popc(bp & lt);
    int nr = neg_base + won + __popc(bn & lt);
    if (f == 1) { if (pr < 128) g_pos_sel[pr] = i; }
    else if (f == 2) { if (nr < 128) g_neg_sel[nr] = i; }
}

static __device__ __forceinline__ float sl1(float x) {
    float ax = fabsf(x);
    return ax < 1.0f ? 0.5f * x * x : ax - 0.5f;
}

// ---------------- K6a: per-positive loss, one warp-block per positive -------
// Spreads the 8192 exact div.rn ops over 128 SMs (was: all on one SM).
__global__ void __launch_bounds__(32) k6a_pos(const float* __restrict__ score,
                                              const float* __restrict__ reg,
                                              const float4* __restrict__ anchors,
                                              const float4* __restrict__ gts) {
    int lane = threadIdx.x;
    int pid = blockIdx.x;

    // npos / bug from pos counts (L2-resident; redundant per block but tiny)
    int tp = 0;
    for (int i = lane; i < NB1; i += 32) tp += g_cnt_pos[i];
    for (int o = 16; o > 0; o >>= 1) tp += __shfl_xor_sync(0xFFFFFFFFu, tp, o);
    int npos = tp < 128 ? tp : 128;
    bool bug = (tp >= 128);

    if (pid >= npos) {
        if (lane == 0) g_pos_loss[pid] = 0.0f;   // deterministic zero fill
        return;
    }
    int ai = g_pos_sel[pid];
    float4 a = anchors[ai];
    float area_a = __fmul_rn(__fsub_rn(a.z, a.x), __fsub_rn(a.w, a.y));

    unsigned long long bk = 0ull;
#pragma unroll
    for (int j = 0; j < 2; ++j) {
        int g = lane + j * 32;
        float4 gb = gts[g];
        float wx = fmaxf(__fsub_rn(fminf(a.z, gb.z), fmaxf(a.x, gb.x)), 0.f);
        float wy = fmaxf(__fsub_rn(fminf(a.w, gb.w), fmaxf(a.y, gb.y)), 0.f);
        float inter = __fmul_rn(wx, wy);
        float agv = __fmul_rn(__fsub_rn(gb.z, gb.x), __fsub_rn(gb.w, gb.y));
        float uni = __fsub_rn(__fadd_rn(area_a, agv), inter);
        float iou = __fdiv_rn(inter, uni);       // exact, matches reference
        // key: max iou wins; ties -> largest (63-g) = smallest g (first occur)
        unsigned long long key =
            ((unsigned long long)(unsigned)__float_as_int(iou) << 6) |
            (unsigned long long)(unsigned)(63 - g);
        bk = u64max(bk, key);
    }
#pragma unroll
    for (int o = 16; o > 0; o >>= 1)
        bk = u64max(bk, __shfl_xor_sync(0xFFFFFFFFu, bk, o));

    if (lane == 0) {
        int bg = 63 - (int)(bk & 63ull);
        float cls;
        if (bug) {  // reference "bug": anchor coords used as 4-way logits
            float v0 = a.x, v1 = a.y, v2 = a.z, v3 = a.w;
            float mx = fmaxf(fmaxf(v0, v1), fmaxf(v2, v3));
            float s = expf(v0 - mx) + expf(v1 - mx) + expf(v2 - mx) + expf(v3 - mx);
            cls = logf(s) - (v0 - mx);
        } else {
            float v0 = score[2 * ai], v1 = score[2 * ai + 1];
            float mx = fmaxf(v0, v1);
            float s = expf(v0 - mx) + expf(v1 - mx);
            cls = logf(s) - (v0 - mx);
        }
        float4 gb = gts[bg];
        float aw = a.z - a.x, ah = a.w - a.y;
        float acx = a.x + aw * 0.5f, acy = a.y + ah * 0.5f;
        float gw = gb.z - gb.x, gh = gb.w - gb.y;
        float gcx = gb.x + gw * 0.5f, gcy = gb.y + gh * 0.5f;
        float tx = (gcx - acx) / aw, ty = (gcy - acy) / ah;
        float tw = logf(gw / aw), th = logf(gh / ah);
        const float* r = reg + 4 * ai;
        float rs = sl1(r[0] - tx) + sl1(r[1] - ty) + sl1(r[2] - tw) + sl1(r[3] - th);
        g_pos_loss[pid] = cls + rs;
    }
}

// ---------------- K6b: negatives + final reduction --------------------------
__global__ void __launch_bounds__(256) k6b_final(const float* __restrict__ score,
                                                 float* __restrict__ out) {
    __shared__ unsigned long long s_tot[8];
    __shared__ float sA[8], sB[8];
    int t = threadIdx.x;
    int lane = t & 31, warp = t >> 5;

    // totals over per-block counts (packed pos | neg<<32)
    unsigned long long tot = 0ull;
    for (int i = t; i < NB1; i += 256)
        tot += (unsigned long long)(unsigned)g_cnt_pos[i] |
               ((unsigned long long)(unsigned)g_cnt_neg[i] << 32);
    for (int o = 16; o > 0; o >>= 1)
        tot += __shfl_down_sync(0xFFFFFFFFu, tot, o);
    if (lane == 0) s_tot[warp] = tot;
    __syncthreads();
    tot = 0ull;
#pragma unroll
    for (int k = 0; k < 8; ++k) tot += s_tot[k];
    int tp = (int)(tot & 0xFFFFFFFFull);
    int tn = (int)(tot >> 32);
    int npos = tp < 128 ? tp : 128;
    int nneg = npos < tn ? npos : tn;      // nbound == npos in both branches

    float a_val = (t < 128) ? g_pos_loss[t] : 0.0f;   // zero beyond npos

    float b_val = 0.f;
    if (t < nneg) {
        int ni = g_neg_sel[t];
        float v0 = score[2 * ni], v1 = score[2 * ni + 1];
        float mx = fmaxf(v0, v1);
        float s = expf(v0 - mx) + expf(v1 - mx);
        b_val = logf(s) - (v1 - mx);   // target = 1
    }

    for (int o = 16; o > 0; o >>= 1) {
        a_val += __shfl_down_sync(0xFFFFFFFFu, a_val, o);
        b_val += __shfl_down_sync(0xFFFFFFFFu, b_val, o);
    }
    if (lane == 0) { sA[warp] = a_val; sB[warp] = b_val; }
    __syncthreads();
    if (t == 0) {
        float av = 0.f, bv = 0.f;
#pragma unroll
        for (int k = 0; k < 8; ++k) { av += sA[k]; bv += sB[k]; }
        out[0] = av / (float)npos + bv / (float)nneg;
    }
}

// ---------------- launch ----------------------------------------------------
extern "C" void kernel_launch(void* const* d_in, const int* in_sizes, int n_in,
                              void* d_out, int out_size) {
    const float* score = (const float*)d_in[0];     // [A,2]
    const float* reg = (const float*)d_in[1];       // [A,4]
    const float4* anchors = (const float4*)d_in[2]; // [A,4]
    const float4* gts = (const float4*)d_in[3];     // [G,4]
    (void)in_sizes; (void)n_in; (void)out_size;

    k1_iou<<<NB1, K1_TPB>>>(anchors, gts);
    k2_gtbest<<<G_N, 256>>>(anchors, gts);
    k5_select<<<NB1, 256>>>();
    k6a_pos<<<128, 32>>>(score, reg, anchors, gts);
    k6b_final<<<1, 256>>>(score, (float*)d_out);
}

// round 11
// speedup vs baseline: 1.4131x; 1.0014x over previous
#include <cuda_runtime.h>

#define A_N 500000
#define G_N 64
#define K1_TPB 256
#define NB1 ((A_N + K1_TPB - 1) / K1_TPB)   /* 1954 */
#define R_FLOOR 0.02f
#define BIN_W 32.0f
#define BIN_INV 0.03125f                    /* 1/32: power of two => exact */

// ---------------- scratch (device globals; no allocations allowed) ----------
__device__ unsigned long long g_blk_best[G_N * NB1]; // per-(gt,block) approx best
__device__ int g_flags[A_N];                         // 0 none, 1 pos, 2 neg
__device__ int g_cnt_pos[NB1], g_cnt_neg[NB1];
__device__ int g_pos_sel[128], g_neg_sel[128];
__device__ float g_pos_loss[128];
__device__ int g_total_pos, g_total_neg;             // written by K5 last block

// named u64max to avoid collision with sbsa math_functions.hpp::ullmax
static __device__ __forceinline__ unsigned long long u64max(unsigned long long a,
                                                            unsigned long long b) {
    return a > b ? a : b;
}

static __device__ __forceinline__ int bin_of(float v) {
    int b = (int)(v * BIN_INV);         // exact scale (power-of-two)
    return b < 0 ? 0 : (b > 31 ? 31 : b);
}

// ---------------- K1: binned IoU sweep -> flags + counts + (gt,block) best --
__global__ void __launch_bounds__(K1_TPB) k1_iou(const float4* __restrict__ anchors,
                                                 const float4* __restrict__ gts) {
    __shared__ float4 s_g[G_N];
    __shared__ float s_area[G_N];
    __shared__ int s_r[G_N];                       // float bits, monotone
    __shared__ unsigned long long s_key[G_N];      // (approx_iou_bits<<32)|rev
    __shared__ unsigned long long s_tbl[4][32];    // Lx, Rx, Ly, Ry
    __shared__ int s_cw[8];

    int t = threadIdx.x;
    if (t < G_N) {
        float4 g = gts[t];
        s_g[t] = g;
        s_area[t] = __fmul_rn(__fsub_rn(g.z, g.x), __fsub_rn(g.w, g.y));
        s_r[t] = __float_as_int(R_FLOOR);
        s_key[t] = 0ull;
    }
    __syncthreads();

    if (t < 128) {                 // build disjointness tables (4 tables x 32)
        int tbl = t >> 5, b = t & 31;
        float eL = (float)b * BIN_W;
        float eR = eL + BIN_W;
        unsigned long long mask = 0ull;
        for (int g = 0; g < G_N; ++g) {
            float4 gb = s_g[g];
            bool out;
            if (tbl == 0)      out = gb.z < eL;   // entirely left  of bin start
            else if (tbl == 1) out = gb.x > eR;   // entirely right of bin end
            else if (tbl == 2) out = gb.w < eL;   // entirely below
            else               out = gb.y > eR;   // entirely above
            mask |= out ? (1ull << g) : 0ull;
        }
        s_tbl[tbl][b] = mask;
    }
    __syncthreads();

    int i = blockIdx.x * K1_TPB + t;
    bool valid = (i < A_N);
    float4 a = valid ? anchors[i] : make_float4(0.f, 0.f, 0.f, 0.f);
    float ar = __fmul_rn(__fsub_rn(a.z, a.x), __fsub_rn(a.w, a.y));
    unsigned rev = 0xFFFFFFFFu - (unsigned)i;

    unsigned long long m =
        ~(s_tbl[0][bin_of(a.x)] | s_tbl[1][bin_of(a.z)] |
          s_tbl[2][bin_of(a.y)] | s_tbl[3][bin_of(a.w)]);
    if (!valid) m = 0ull;

    float posm = -1.f, negm = -1.f;
    while (m) {
        int g = __ffsll((long long)m) - 1;
        m &= m - 1ull;
        float4 gb = s_g[g];
        float wx = fmaxf(__fsub_rn(fminf(a.z, gb.z), fmaxf(a.x, gb.x)), 0.f);
        float wy = fmaxf(__fsub_rn(fminf(a.w, gb.w), fmaxf(a.y, gb.y)), 0.f);
        float inter = __fmul_rn(wx, wy);
        float uni = __fsub_rn(__fadd_rn(ar, s_area[g]), inter);
        posm = fmaxf(posm, __fmaf_rn(2.0f, inter, -uni));   // sign <=> iou>0.5
        negm = fmaxf(negm, __fmaf_rn(-0.3f, uni, inter));   // sign <=> iou>=0.3
        int ival = __float_as_int(__fdividef(inter, uni));  // ranking key only
        if (ival >= s_r[g]) {   // iou<R_FLOOR auto-fails; >= keeps tie lower idx
            atomicMax(&s_r[g], ival);
            atomicMax(&s_key[g], ((unsigned long long)(unsigned)ival << 32) |
                                 (unsigned long long)rev);
        }
    }

    int f = (posm > 0.0f) ? 1 : ((negm < 0.0f) ? 2 : 0);
    if (valid) g_flags[i] = f;
    if (!valid) f = 0;

    // per-block pos/neg counts via ballots (K2 patches forced positives)
    unsigned bp = __ballot_sync(0xFFFFFFFFu, f == 1);
    unsigned bn = __ballot_sync(0xFFFFFFFFu, f == 2);
    if ((t & 31) == 0) s_cw[t >> 5] = __popc(bp) | (__popc(bn) << 16);
    __syncthreads();   // also orders s_key/s_r atomics before the export below
    if (t < G_N) g_blk_best[t * NB1 + blockIdx.x] = s_key[t];
    if (t == 0) {
        int tot = 0;
#pragma unroll
        for (int k = 0; k < 8; ++k) tot += s_cw[k];
        g_cnt_pos[blockIdx.x] = tot & 0xFFFF;
        g_cnt_neg[blockIdx.x] = tot >> 16;
    }
}

// ---------------- K2: per-GT exact argmax -> force positive + patch counts --
__global__ void __launch_bounds__(256) k2_gtbest(const float4* __restrict__ anchors,
                                                 const float4* __restrict__ gts) {
    __shared__ unsigned long long s[256];
    int g = blockIdx.x, t = threadIdx.x;
    float4 gb = gts[g];
    float ag = __fmul_rn(__fsub_rn(gb.z, gb.x), __fsub_rn(gb.w, gb.y));

    unsigned long long best = 0ull;
    const unsigned long long* row = g_blk_best + (size_t)g * NB1;
    for (int b = t; b < NB1; b += 256) {
        unsigned long long k = row[b];
        if (k == 0ull) continue;
        unsigned idx = 0xFFFFFFFFu - (unsigned)(k & 0xFFFFFFFFull);
        if (idx >= A_N) continue;
        float4 a = anchors[idx];
        float area_a = __fmul_rn(__fsub_rn(a.z, a.x), __fsub_rn(a.w, a.y));
        float wx = fmaxf(__fsub_rn(fminf(a.z, gb.z), fmaxf(a.x, gb.x)), 0.f);
        float wy = fmaxf(__fsub_rn(fminf(a.w, gb.w), fmaxf(a.y, gb.y)), 0.f);
        float inter = __fmul_rn(wx, wy);
        float uni = __fsub_rn(__fadd_rn(area_a, ag), inter);
        float iou = __fdiv_rn(inter, uni);   // exact (matches reference bits)
        unsigned long long key =
            ((unsigned long long)(unsigned)__float_as_int(iou) << 32) |
            (unsigned long long)(0xFFFFFFFFu - idx);
        best = u64max(best, key);
    }
    s[t] = best;
    __syncthreads();
    for (int o = 128; o > 0; o >>= 1) {
        if (t < o) s[t] = u64max(s[t], s[t + o]);
        __syncthreads();
    }
    if (t == 0 && s[0] != 0ull) {
        unsigned idx = 0xFFFFFFFFu - (unsigned)(s[0] & 0xFFFFFFFFull);
        if (idx < A_N) {
            int old = atomicExch(&g_flags[idx], 1);  // exactly-once vs dup gts
            if (old != 1) {
                int b = (int)(idx / K1_TPB);
                atomicAdd(&g_cnt_pos[b], 1);
                if (old == 2) atomicSub(&g_cnt_neg[b], 1);
            }
        }
    }
}

// ---------------- K5: ordered first-128 compaction w/ inline prefix ---------
// Last block (b == NB1-1) additionally publishes grand totals for K6a/K6b.
__global__ void __launch_bounds__(256) k5_select() {
    __shared__ unsigned long long s_pref[8];
    __shared__ int s_wp[8], s_wn[8];
    int b = blockIdx.x, t = threadIdx.x;
    int lane = t & 31, warp = t >> 5;

    // exclusive prefix of counts [0, b), packed pos|neg<<32
    unsigned long long pref = 0ull;
    for (int i = t; i < b; i += 256)
        pref += (unsigned long long)(unsigned)g_cnt_pos[i] |
                ((unsigned long long)(unsigned)g_cnt_neg[i] << 32);
    for (int o = 16; o > 0; o >>= 1)
        pref += __shfl_down_sync(0xFFFFFFFFu, pref, o);
    if (lane == 0) s_pref[warp] = pref;
    __syncthreads();
    unsigned long long tot = 0ull;
#pragma unroll
    for (int k = 0; k < 8; ++k) tot += s_pref[k];
    int pos_base = (int)(tot & 0xFFFFFFFFull);
    int neg_base = (int)(tot >> 32);

    if (b == NB1 - 1 && t == 0) {         // publish totals BEFORE early exit
        g_total_pos = pos_base + g_cnt_pos[b];
        g_total_neg = neg_base + g_cnt_neg[b];
    }
    if (pos_base >= 128 && neg_base >= 128) return;  // uniform per-block exit

    int i = b * K1_TPB + t;
    int f = (i < A_N) ? g_flags[i] : 0;
    unsigned bp = __ballot_sync(0xFFFFFFFFu, f == 1);
    unsigned bn = __ballot_sync(0xFFFFFFFFu, f == 2);
    if (lane == 0) { s_wp[warp] = __popc(bp); s_wn[warp] = __popc(bn); }
    __syncthreads();
    int wop = 0, won = 0;
    for (int k = 0; k < warp; ++k) { wop += s_wp[k]; won += s_wn[k]; }
    unsigned lt = (1u << lane) - 1u;
    int pr = pos_base + wop + __popc(bp & lt);
    int nr = neg_base + won + __popc(bn & lt);
    if (f == 1) { if (pr < 128) g_pos_sel[pr] = i; }
    else if (f == 2) { if (nr < 128) g_neg_sel[nr] = i; }
}

static __device__ __forceinline__ float sl1(float x) {
    float ax = fabsf(x);
    return ax < 1.0f ? 0.5f * x * x : ax - 0.5f;
}

// ---------------- K6a: per-positive loss, one warp-block per positive -------
__global__ void __launch_bounds__(32) k6a_pos(const float* __restrict__ score,
                                              const float* __restrict__ reg,
                                              const float4* __restrict__ anchors,
                                              const float4* __restrict__ gts) {
    int lane = threadIdx.x;
    int pid = blockIdx.x;

    int tp = g_total_pos;                 // precomputed by K5 (one L2 load)
    int npos = tp < 128 ? tp : 128;
    bool bug = (tp >= 128);

    if (pid >= npos) {
        if (lane == 0) g_pos_loss[pid] = 0.0f;   // deterministic zero fill
        return;
    }
    int ai = g_pos_sel[pid];
    float4 a = anchors[ai];
    float area_a = __fmul_rn(__fsub_rn(a.z, a.x), __fsub_rn(a.w, a.y));

    unsigned long long bk = 0ull;
#pragma unroll
    for (int j = 0; j < 2; ++j) {
        int g = lane + j * 32;
        float4 gb = gts[g];
        float wx = fmaxf(__fsub_rn(fminf(a.z, gb.z), fmaxf(a.x, gb.x)), 0.f);
        float wy = fmaxf(__fsub_rn(fminf(a.w, gb.w), fmaxf(a.y, gb.y)), 0.f);
        float inter = __fmul_rn(wx, wy);
        float agv = __fmul_rn(__fsub_rn(gb.z, gb.x), __fsub_rn(gb.w, gb.y));
        float uni = __fsub_rn(__fadd_rn(area_a, agv), inter);
        float iou = __fdiv_rn(inter, uni);       // exact, matches reference
        // key: max iou wins; ties -> largest (63-g) = smallest g (first occur)
        unsigned long long key =
            ((unsigned long long)(unsigned)__float_as_int(iou) << 6) |
            (unsigned long long)(unsigned)(63 - g);
        bk = u64max(bk, key);
    }
#pragma unroll
    for (int o = 16; o > 0; o >>= 1)
        bk = u64max(bk, __shfl_xor_sync(0xFFFFFFFFu, bk, o));

    if (lane == 0) {
        int bg = 63 - (int)(bk & 63ull);
        float cls;
        if (bug) {  // reference "bug": anchor coords used as 4-way logits
            float v0 = a.x, v1 = a.y, v2 = a.z, v3 = a.w;
            float mx = fmaxf(fmaxf(v0, v1), fmaxf(v2, v3));
            float s = expf(v0 - mx) + expf(v1 - mx) + expf(v2 - mx) + expf(v3 - mx);
            cls = logf(s) - (v0 - mx);
        } else {
            float v0 = score[2 * ai], v1 = score[2 * ai + 1];
            float mx = fmaxf(v0, v1);
            float s = expf(v0 - mx) + expf(v1 - mx);
            cls = logf(s) - (v0 - mx);
        }
        float4 gb = gts[bg];
        float aw = a.z - a.x, ah = a.w - a.y;
        float acx = a.x + aw * 0.5f, acy = a.y + ah * 0.5f;
        float gw = gb.z - gb.x, gh = gb.w - gb.y;
        float gcx = gb.x + gw * 0.5f, gcy = gb.y + gh * 0.5f;
        float tx = (gcx - acx) / aw, ty = (gcy - acy) / ah;
        float tw = logf(gw / aw), th = logf(gh / ah);
        const float* r = reg + 4 * ai;
        float rs = sl1(r[0] - tx) + sl1(r[1] - ty) + sl1(r[2] - tw) + sl1(r[3] - th);
        g_pos_loss[pid] = cls + rs;
    }
}

// ---------------- K6b: negatives + final reduction --------------------------
__global__ void __launch_bounds__(128) k6b_final(const float* __restrict__ score,
                                                 float* __restrict__ out) {
    __shared__ float sA[4], sB[4];
    int t = threadIdx.x;
    int lane = t & 31, warp = t >> 5;

    int tp = g_total_pos;                 // precomputed by K5
    int tn = g_total_neg;
    int npos = tp < 128 ? tp : 128;
    int nneg = npos < tn ? npos : tn;     // nbound == npos in both branches

    float a_val = g_pos_loss[t];          // zeroed beyond npos by K6a

    float b_val = 0.f;
    if (t < nneg) {
        int ni = g_neg_sel[t];
        float v0 = score[2 * ni], v1 = score[2 * ni + 1];
        float mx = fmaxf(v0, v1);
        float s = expf(v0 - mx) + expf(v1 - mx);
        b_val = logf(s) - (v1 - mx);   // target = 1
    }

    for (int o = 16; o > 0; o >>= 1) {
        a_val += __shfl_down_sync(0xFFFFFFFFu, a_val, o);
        b_val += __shfl_down_sync(0xFFFFFFFFu, b_val, o);
    }
    if (lane == 0) { sA[warp] = a_val; sB[warp] = b_val; }
    __syncthreads();
    if (t == 0) {
        float av = sA[0] + sA[1] + sA[2] + sA[3];
        float bv = sB[0] + sB[1] + sB[2] + sB[3];
        out[0] = av / (float)npos + bv / (float)nneg;
    }
}

// ---------------- launch ----------------------------------------------------
extern "C" void kernel_launch(void* const* d_in, const int* in_sizes, int n_in,
                              void* d_out, int out_size) {
    const float* score = (const float*)d_in[0];     // [A,2]
    const float* reg = (const float*)d_in[1];       // [A,4]
    const float4* anchors = (const float4*)d_in[2]; // [A,4]
    const float4* gts = (const float4*)d_in[3];     // [G,4]
    (void)in_sizes; (void)n_in; (void)out_size;

    k1_iou<<<NB1, K1_TPB>>>(anchors, gts);
    k2_gtbest<<<G_N, 256>>>(anchors, gts);
    k5_select<<<NB1, 256>>>();
    k6a_pos<<<128, 32>>>(score, reg, anchors, gts);
    k6b_final<<<1, 128>>>(score, (float*)d_out);
}

// round 14
// speedup vs baseline: 1.5494x; 1.0965x over previous
#include <cuda_runtime.h>

#define A_N 500000
#define G_N 64
#define K1_TPB 512
#define NB1 ((A_N + K1_TPB - 1) / K1_TPB)   /* 977 */
#define R_FLOOR 0.02f
#define BIN_W 32.0f
#define BIN_INV 0.03125f                    /* 1/32: power of two => exact */

// ---------------- scratch (device globals; no allocations allowed) ----------
__device__ unsigned long long g_blk_best[G_N * NB1]; // per-(gt,block) approx best
__device__ int g_flags[A_N];                         // 0 none, 1 pos, 2 neg
__device__ int g_cnt_pos[NB1], g_cnt_neg[NB1];
__device__ int g_pos_sel[128], g_neg_sel[128];
__device__ float g_pos_loss[128];
__device__ int g_total_pos, g_total_neg;             // written by K5 last block
__device__ int g_done = 0;                           // K6 completion counter

// named u64max to avoid collision with sbsa math_functions.hpp::ullmax
static __device__ __forceinline__ unsigned long long u64max(unsigned long long a,
                                                            unsigned long long b) {
    return a > b ? a : b;
}

static __device__ __forceinline__ int bin_of(float v) {
    int b = (int)(v * BIN_INV);         // exact scale (power-of-two)
    return b < 0 ? 0 : (b > 31 ? 31 : b);
}

// ---------------- K1: binned IoU sweep -> flags + counts + (gt,block) best --
__global__ void __launch_bounds__(K1_TPB) k1_iou(const float4* __restrict__ anchors,
                                                 const float4* __restrict__ gts) {
    __shared__ float4 s_g[G_N];
    __shared__ float s_area[G_N];
    __shared__ int s_r[G_N];                       // float bits, monotone
    __shared__ unsigned long long s_key[G_N];      // (approx_iou_bits<<32)|rev
    __shared__ unsigned long long s_tbl[4][32];    // Lx, Rx, Ly, Ry
    __shared__ int s_cw[16];

    int t = threadIdx.x;
    if (t < G_N) {
        float4 g = gts[t];
        s_g[t] = g;
        s_area[t] = __fmul_rn(__fsub_rn(g.z, g.x), __fsub_rn(g.w, g.y));
        s_r[t] = __float_as_int(R_FLOOR);
        s_key[t] = 0ull;
    }
    __syncthreads();

    if (t < 128) {                 // build disjointness tables (4 tables x 32)
        int tbl = t >> 5, b = t & 31;
        float eL = (float)b * BIN_W;
        float eR = eL + BIN_W;
        unsigned long long mask = 0ull;
        for (int g = 0; g < G_N; ++g) {
            float4 gb = s_g[g];
            bool out;
            if (tbl == 0)      out = gb.z < eL;   // entirely left  of bin start
            else if (tbl == 1) out = gb.x > eR;   // entirely right of bin end
            else if (tbl == 2) out = gb.w < eL;   // entirely below
            else               out = gb.y > eR;   // entirely above
            mask |= out ? (1ull << g) : 0ull;
        }
        s_tbl[tbl][b] = mask;
    }
    __syncthreads();

    int i = blockIdx.x * K1_TPB + t;
    bool valid = (i < A_N);
    float4 a = valid ? anchors[i] : make_float4(0.f, 0.f, 0.f, 0.f);
    float ar = __fmul_rn(__fsub_rn(a.z, a.x), __fsub_rn(a.w, a.y));
    unsigned rev = 0xFFFFFFFFu - (unsigned)i;

    unsigned long long m =
        ~(s_tbl[0][bin_of(a.x)] | s_tbl[1][bin_of(a.z)] |
          s_tbl[2][bin_of(a.y)] | s_tbl[3][bin_of(a.w)]);
    if (!valid) m = 0ull;

    float posm = -1.f, negm = -1.f;
    while (m) {
        int g = __ffsll((long long)m) - 1;
        m &= m - 1ull;
        float4 gb = s_g[g];
        float wx = fmaxf(__fsub_rn(fminf(a.z, gb.z), fmaxf(a.x, gb.x)), 0.f);
        float wy = fmaxf(__fsub_rn(fminf(a.w, gb.w), fmaxf(a.y, gb.y)), 0.f);
        float inter = __fmul_rn(wx, wy);
        float uni = __fsub_rn(__fadd_rn(ar, s_area[g]), inter);
        posm = fmaxf(posm, __fmaf_rn(2.0f, inter, -uni));   // sign <=> iou>0.5
        negm = fmaxf(negm, __fmaf_rn(-0.3f, uni, inter));   // sign <=> iou>=0.3
        int ival = __float_as_int(__fdividef(inter, uni));  // ranking key only
        if (ival >= s_r[g]) {   // iou<R_FLOOR auto-fails; >= keeps tie lower idx
            atomicMax(&s_r[g], ival);
            atomicMax(&s_key[g], ((unsigned long long)(unsigned)ival << 32) |
                                 (unsigned long long)rev);
        }
    }

    int f = (posm > 0.0f) ? 1 : ((negm < 0.0f) ? 2 : 0);
    if (valid) g_flags[i] = f;
    if (!valid) f = 0;

    // per-block pos/neg counts via ballots (K2 patches forced positives)
    unsigned bp = __ballot_sync(0xFFFFFFFFu, f == 1);
    unsigned bn = __ballot_sync(0xFFFFFFFFu, f == 2);
    if ((t & 31) == 0) s_cw[t >> 5] = __popc(bp) | (__popc(bn) << 16);
    __syncthreads();   // also orders s_key/s_r atomics before the export below
    if (t < G_N) g_blk_best[t * NB1 + blockIdx.x] = s_key[t];
    if (t == 0) {
        int tot = 0;
#pragma unroll
        for (int k = 0; k < 16; ++k) tot += s_cw[k];
        g_cnt_pos[blockIdx.x] = tot & 0xFFFF;
        g_cnt_neg[blockIdx.x] = tot >> 16;
    }
}

// ---------------- K2: per-GT exact argmax -> force positive + patch counts --
__global__ void __launch_bounds__(256) k2_gtbest(const float4* __restrict__ anchors,
                                                 const float4* __restrict__ gts) {
    __shared__ unsigned long long s[256];
    int g = blockIdx.x, t = threadIdx.x;
    float4 gb = gts[g];
    float ag = __fmul_rn(__fsub_rn(gb.z, gb.x), __fsub_rn(gb.w, gb.y));

    unsigned long long best = 0ull;
    const unsigned long long* row = g_blk_best + (size_t)g * NB1;
    for (int b = t; b < NB1; b += 256) {
        unsigned long long k = row[b];
        if (k == 0ull) continue;
        unsigned idx = 0xFFFFFFFFu - (unsigned)(k & 0xFFFFFFFFull);
        if (idx >= A_N) continue;
        float4 a = anchors[idx];
        float area_a = __fmul_rn(__fsub_rn(a.z, a.x), __fsub_rn(a.w, a.y));
        float wx = fmaxf(__fsub_rn(fminf(a.z, gb.z), fmaxf(a.x, gb.x)), 0.f);
        float wy = fmaxf(__fsub_rn(fminf(a.w, gb.w), fmaxf(a.y, gb.y)), 0.f);
        float inter = __fmul_rn(wx, wy);
        float uni = __fsub_rn(__fadd_rn(area_a, ag), inter);
        float iou = __fdiv_rn(inter, uni);   // exact (matches reference bits)
        unsigned long long key =
            ((unsigned long long)(unsigned)__float_as_int(iou) << 32) |
            (unsigned long long)(0xFFFFFFFFu - idx);
        best = u64max(best, key);
    }
    s[t] = best;
    __syncthreads();
    for (int o = 128; o > 0; o >>= 1) {
        if (t < o) s[t] = u64max(s[t], s[t + o]);
        __syncthreads();
    }
    if (t == 0 && s[0] != 0ull) {
        unsigned idx = 0xFFFFFFFFu - (unsigned)(s[0] & 0xFFFFFFFFull);
        if (idx < A_N) {
            int old = atomicExch(&g_flags[idx], 1);  // exactly-once vs dup gts
            if (old != 1) {
                int b = (int)(idx / K1_TPB);
                atomicAdd(&g_cnt_pos[b], 1);
                if (old == 2) atomicSub(&g_cnt_neg[b], 1);
            }
        }
    }
}

// ---------------- K5: ordered first-128 compaction w/ inline prefix ---------
// Last block (b == NB1-1) additionally publishes grand totals for K6.
__global__ void __launch_bounds__(K1_TPB) k5_select() {
    __shared__ unsigned long long s_pref[16];
    __shared__ int s_wp[16], s_wn[16];
    int b = blockIdx.x, t = threadIdx.x;
    int lane = t & 31, warp = t >> 5;

    // exclusive prefix of counts [0, b), packed pos|neg<<32
    unsigned long long pref = 0ull;
    for (int i = t; i < b; i += K1_TPB)
        pref += (unsigned long long)(unsigned)g_cnt_pos[i] |
                ((unsigned long long)(unsigned)g_cnt_neg[i] << 32);
    for (int o = 16; o > 0; o >>= 1)
        pref += __shfl_down_sync(0xFFFFFFFFu, pref, o);
    if (lane == 0) s_pref[warp] = pref;
    __syncthreads();
    unsigned long long tot = 0ull;
#pragma unroll
    for (int k = 0; k < 16; ++k) tot += s_pref[k];
    int pos_base = (int)(tot & 0xFFFFFFFFull);
    int neg_base = (int)(tot >> 32);

    if (b == NB1 - 1 && t == 0) {         // publish totals BEFORE early exit
        g_total_pos = pos_base + g_cnt_pos[b];
        g_total_neg = neg_base + g_cnt_neg[b];
    }
    if (pos_base >= 128 && neg_base >= 128) return;  // uniform per-block exit

    int i = b * K1_TPB + t;
    int f = (i < A_N) ? g_flags[i] : 0;
    unsigned bp = __ballot_sync(0xFFFFFFFFu, f == 1);
    unsigned bn = __ballot_sync(0xFFFFFFFFu, f == 2);
    if (lane == 0) { s_wp[warp] = __popc(bp); s_wn[warp] = __popc(bn); }
    __syncthreads();
    int wop = 0, won = 0;
    for (int k = 0; k < warp; ++k) { wop += s_wp[k]; won += s_wn[k]; }
    unsigned lt = (1u << lane) - 1u;
    int pr = pos_base + wop + __popc(bp & lt);
    int nr = neg_base + won + __popc(bn & lt);
    if (f == 1) { if (pr < 128) g_pos_sel[pr] = i; }
    else if (f == 2) { if (nr < 128) g_neg_sel[nr] = i; }
}

static __device__ __forceinline__ float sl1(float x) {
    float ax = fabsf(x);
    return ax < 1.0f ? 0.5f * x * x : ax - 0.5f;
}

// ---------------- K6: fused positive losses + final reduction ---------------
// 128 warp-blocks compute per-positive losses; the LAST block to finish
// (completion counter) performs the negative CE + final scalar reduction.
__global__ void __launch_bounds__(32) k6_fused(const float* __restrict__ score,
                                               const float* __restrict__ reg,
                                               const float4* __restrict__ anchors,
                                               const float4* __restrict__ gts,
                                               float* __restrict__ out) {
    int lane = threadIdx.x;
    int pid = blockIdx.x;

    // kick independent loads early (sel clamped: slot may be stale/garbage
    // on the very first run when pid >= npos -- discarded below)
    int sel = g_pos_sel[pid & 127];
    int tp = g_total_pos;
    int ai = sel < 0 ? 0 : (sel >= A_N ? A_N - 1 : sel);
    float4 a = anchors[ai];

    int npos = tp < 128 ? tp : 128;
    bool bug = (tp >= 128);

    if (pid < npos) {
        float area_a = __fmul_rn(__fsub_rn(a.z, a.x), __fsub_rn(a.w, a.y));
        unsigned long long bk = 0ull;
#pragma unroll
        for (int j = 0; j < 2; ++j) {
            int g = lane + j * 32;
            float4 gb = gts[g];
            float wx = fmaxf(__fsub_rn(fminf(a.z, gb.z), fmaxf(a.x, gb.x)), 0.f);
            float wy = fmaxf(__fsub_rn(fminf(a.w, gb.w), fmaxf(a.y, gb.y)), 0.f);
            float inter = __fmul_rn(wx, wy);
            float agv = __fmul_rn(__fsub_rn(gb.z, gb.x), __fsub_rn(gb.w, gb.y));
            float uni = __fsub_rn(__fadd_rn(area_a, agv), inter);
            float iou = __fdiv_rn(inter, uni);       // exact, matches reference
            // key: max iou wins; ties -> largest (63-g) = smallest g (first)
            unsigned long long key =
                ((unsigned long long)(unsigned)__float_as_int(iou) << 6) |
                (unsigned long long)(unsigned)(63 - g);
            bk = u64max(bk, key);
        }
#pragma unroll
        for (int o = 16; o > 0; o >>= 1)
            bk = u64max(bk, __shfl_xor_sync(0xFFFFFFFFu, bk, o));

        if (lane == 0) {
            int bg = 63 - (int)(bk & 63ull);
            float cls;
            if (bug) {  // reference "bug": anchor coords used as 4-way logits
                float v0 = a.x, v1 = a.y, v2 = a.z, v3 = a.w;
                float mx = fmaxf(fmaxf(v0, v1), fmaxf(v2, v3));
                float s = expf(v0 - mx) + expf(v1 - mx) + expf(v2 - mx) + expf(v3 - mx);
                cls = logf(s) - (v0 - mx);
            } else {
                float v0 = score[2 * ai], v1 = score[2 * ai + 1];
                float mx = fmaxf(v0, v1);
                float s = expf(v0 - mx) + expf(v1 - mx);
                cls = logf(s) - (v0 - mx);
            }
            float4 gb = gts[bg];
            float aw = a.z - a.x, ah = a.w - a.y;
            float acx = a.x + aw * 0.5f, acy = a.y + ah * 0.5f;
            float gw = gb.z - gb.x, gh = gb.w - gb.y;
            float gcx = gb.x + gw * 0.5f, gcy = gb.y + gh * 0.5f;
            float tx = (gcx - acx) / aw, ty = (gcy - acy) / ah;
            float tw = logf(gw / aw), th = logf(gh / ah);
            const float* r = reg + 4 * ai;
            float rs = sl1(r[0] - tx) + sl1(r[1] - ty) + sl1(r[2] - tw) + sl1(r[3] - th);
            g_pos_loss[pid] = cls + rs;
        }
    } else {
        if (lane == 0) g_pos_loss[pid] = 0.0f;   // deterministic zero fill
    }

    // completion counter: last-arriving block performs final reduction
    __threadfence();
    int is_last = 0;
    if (lane == 0) is_last = (atomicAdd(&g_done, 1) == gridDim.x - 1);
    is_last = __shfl_sync(0xFFFFFFFFu, is_last, 0);
    if (!is_last) return;

    int tn = g_total_neg;
    int nneg = npos < tn ? npos : tn;     // nbound == npos in both branches

    float a_val = 0.f, b_val = 0.f;
#pragma unroll
    for (int j = 0; j < 4; ++j) {
        int idx = lane + j * 32;
        a_val += g_pos_loss[idx];         // zeroed beyond npos
        if (idx < nneg) {
            int ni = g_neg_sel[idx];
            float v0 = score[2 * ni], v1 = score[2 * ni + 1];
            float mx = fmaxf(v0, v1);
            float s = expf(v0 - mx) + expf(v1 - mx);
            b_val += logf(s) - (v1 - mx);  // target = 1
        }
    }
#pragma unroll
    for (int o = 16; o > 0; o >>= 1) {
        a_val += __shfl_down_sync(0xFFFFFFFFu, a_val, o);
        b_val += __shfl_down_sync(0xFFFFFFFFu, b_val, o);
    }
    if (lane == 0) {
        out[0] = a_val / (float)npos + b_val / (float)nneg;
        g_done = 0;                        // reset for next graph replay
    }
}

// ---------------- launch ----------------------------------------------------
extern "C" void kernel_launch(void* const* d_in, const int* in_sizes, int n_in,
                              void* d_out, int out_size) {
    const float* score = (const float*)d_in[0];     // [A,2]
    const float* reg = (const float*)d_in[1];       // [A,4]
    const float4* anchors = (const float4*)d_in[2]; // [A,4]
    const float4* gts = (const float4*)d_in[3];     // [G,4]
    (void)in_sizes; (void)n_in; (void)out_size;

    k1_iou<<<NB1, K1_TPB>>>(anchors, gts);
    k2_gtbest<<<G_N, 256>>>(anchors, gts);
    k5_select<<<NB1, K1_TPB>>>();
    k6_fused<<<128, 32>>>(score, reg, anchors, gts, (float*)d_out);
}